// round 3
// baseline (speedup 1.0000x reference)
#include <cuda_runtime.h>

#define NN 100000
#define EE 1600000
#define IND 128
#define HIDD 64
#define NC 40

#define EGRID 1184
#define ETPB 256
#define EWPB (ETPB / 32)
#define EWARPS (EGRID * EWPB)
#define NMAXBLK 128

// ---------------- device scratch (float4-typed => 16B aligned) ----------------
__device__ float4 g_h0[NN * (HIDD / 4)];
__device__ float4 g_h1[NN * (HIDD / 4)];
__device__ float4 g_wh[NN * (HIDD / 4)];
__device__ float4 g_hacc[NN * (HIDD / 4)];
__device__ float  g_ssrc[NN];
__device__ float  g_sdst[NN];
__device__ float  g_pmax_s[NMAXBLK];
__device__ float  g_pmax_d[NMAXBLK];
__device__ float  g_psum[EGRID];
__device__ float  g_red[2];   // [0] = shift B, [1] = softmax denominator
__device__ int    g_is64;     // 1 if edge_index is int64, 0 if int32

// ---------------- dtype detector ----------------
// int64 node ids are < 2^31 and nonnegative => every odd 32-bit word is 0.
__global__ void k_detect(const int* __restrict__ ei32) {
    int nz = 0;
    for (int i = threadIdx.x; i < 1024; i += blockDim.x)
        if (ei32[2 * i + 1] != 0) nz = 1;
    int cnt = __syncthreads_count(nz);
    if (threadIdx.x == 0) g_is64 = (cnt == 0) ? 1 : 0;
}

// ---------------- zero accumulator ----------------
__global__ void k_zero_hacc() {
    int t = blockIdx.x * blockDim.x + threadIdx.x;
    if (t < NN * (HIDD / 4)) g_hacc[t] = make_float4(0.f, 0.f, 0.f, 0.f);
}

// ---------------- embedding GEMM: h0 = x @ emb_w + emb_b ----------------
__global__ void __launch_bounds__(128) k_emb(const float* __restrict__ x,
                                             const float* __restrict__ w,
                                             const float* __restrict__ b) {
    __shared__ float sW[IND * HIDD];   // 32 KB
    __shared__ float sb[HIDD];
    int tid = threadIdx.x;
    for (int i = tid; i < IND * HIDD; i += blockDim.x) sW[i] = w[i];
    for (int i = tid; i < HIDD; i += blockDim.x) sb[i] = b[i];
    __syncthreads();

    int node = blockIdx.x * blockDim.x + tid;
    if (node >= NN) return;

    float acc[HIDD];
#pragma unroll
    for (int j = 0; j < HIDD; j++) acc[j] = sb[j];

    const float* xr = x + (size_t)node * IND;
    for (int k = 0; k < IND; k += 4) {
        float h0 = xr[k], h1 = xr[k + 1], h2 = xr[k + 2], h3 = xr[k + 3];
        const float* w0 = &sW[(k + 0) * HIDD];
        const float* w1 = &sW[(k + 1) * HIDD];
        const float* w2 = &sW[(k + 2) * HIDD];
        const float* w3 = &sW[(k + 3) * HIDD];
#pragma unroll
        for (int j = 0; j < HIDD; j++)
            acc[j] += h0 * w0[j] + h1 * w1[j] + h2 * w2[j] + h3 * w3[j];
    }

    float4* orow = g_h0 + (size_t)node * (HIDD / 4);
#pragma unroll
    for (int j4 = 0; j4 < HIDD / 4; j4++)
        orow[j4] = make_float4(acc[4 * j4], acc[4 * j4 + 1], acc[4 * j4 + 2], acc[4 * j4 + 3]);
}

// ---------------- per-layer GEMM + attention scores ----------------
__global__ void __launch_bounds__(128) k_gemm_s(int in_sel,
                                                const float* __restrict__ W,
                                                const float* __restrict__ avec) {
    __shared__ float sW[HIDD * HIDD];  // 16 KB
    __shared__ float sa[2 * HIDD];
    int tid = threadIdx.x;
    for (int i = tid; i < HIDD * HIDD; i += blockDim.x) sW[i] = W[i];
    for (int i = tid; i < 2 * HIDD; i += blockDim.x) sa[i] = avec[i];
    __syncthreads();

    int node = blockIdx.x * blockDim.x + tid;
    if (node >= NN) return;

    const float4* hr = (in_sel ? g_h1 : g_h0) + (size_t)node * (HIDD / 4);

    float acc[HIDD];
#pragma unroll
    for (int j = 0; j < HIDD; j++) acc[j] = 0.0f;

    for (int k4 = 0; k4 < HIDD / 4; k4++) {
        float4 hv = hr[k4];
        const float* w0 = &sW[(k4 * 4 + 0) * HIDD];
        const float* w1 = &sW[(k4 * 4 + 1) * HIDD];
        const float* w2 = &sW[(k4 * 4 + 2) * HIDD];
        const float* w3 = &sW[(k4 * 4 + 3) * HIDD];
#pragma unroll
        for (int j = 0; j < HIDD; j++)
            acc[j] += hv.x * w0[j] + hv.y * w1[j] + hv.z * w2[j] + hv.w * w3[j];
    }

    float ss = 0.0f, sd = 0.0f;
#pragma unroll
    for (int j = 0; j < HIDD; j++) {
        ss += acc[j] * sa[j];
        sd += acc[j] * sa[HIDD + j];
    }
    float4* wr = g_wh + (size_t)node * (HIDD / 4);
#pragma unroll
    for (int j4 = 0; j4 < HIDD / 4; j4++)
        wr[j4] = make_float4(acc[4 * j4], acc[4 * j4 + 1], acc[4 * j4 + 2], acc[4 * j4 + 3]);
    g_ssrc[node] = ss;
    g_sdst[node] = sd;
}

// ---------------- node-level max partials ----------------
__global__ void k_nodemax() {
    float ms = -3.4e38f, md = -3.4e38f;
    for (int i = blockIdx.x * blockDim.x + threadIdx.x; i < NN; i += gridDim.x * blockDim.x) {
        ms = fmaxf(ms, g_ssrc[i]);
        md = fmaxf(md, g_sdst[i]);
    }
#pragma unroll
    for (int o = 16; o; o >>= 1) {
        ms = fmaxf(ms, __shfl_xor_sync(0xffffffffu, ms, o));
        md = fmaxf(md, __shfl_xor_sync(0xffffffffu, md, o));
    }
    __shared__ float sms[8], smd[8];
    int w = threadIdx.x >> 5;
    if ((threadIdx.x & 31) == 0) { sms[w] = ms; smd[w] = md; }
    __syncthreads();
    if (threadIdx.x == 0) {
        float a = sms[0], b2 = smd[0];
        for (int i = 1; i < 8; i++) { a = fmaxf(a, sms[i]); b2 = fmaxf(b2, smd[i]); }
        g_pmax_s[blockIdx.x] = a;
        g_pmax_d[blockIdx.x] = b2;
    }
}

__global__ void k_reduce_shift() {
    // single block, 128 threads over NMAXBLK=128 partials
    float a = g_pmax_s[threadIdx.x];
    float b = g_pmax_d[threadIdx.x];
#pragma unroll
    for (int o = 16; o; o >>= 1) {
        a = fmaxf(a, __shfl_xor_sync(0xffffffffu, a, o));
        b = fmaxf(b, __shfl_xor_sync(0xffffffffu, b, o));
    }
    __shared__ float sa[4], sb[4];
    int w = threadIdx.x >> 5;
    if ((threadIdx.x & 31) == 0) { sa[w] = a; sb[w] = b; }
    __syncthreads();
    if (threadIdx.x == 0) {
        float ma = fmaxf(fmaxf(sa[0], sa[1]), fmaxf(sa[2], sa[3]));
        float mb = fmaxf(fmaxf(sb[0], sb[1]), fmaxf(sb[2], sb[3]));
        g_red[0] = ma + mb;   // B >= max over all (src,dst) score sums
    }
}

// ---------------- fused edge pass: p = exp(s - B) (masked), scatter, partial sum ----------------
__global__ void __launch_bounds__(ETPB) k_edge(const void* __restrict__ ei_raw) {
    const float B = g_red[0];
    const int is64 = g_is64;
    const long long* ei64 = (const long long*)ei_raw;
    const int* ei32 = (const int*)ei_raw;

    int lane = threadIdx.x & 31;
    int wid = threadIdx.x >> 5;
    int gw = blockIdx.x * EWPB + wid;

    const float* whf = reinterpret_cast<const float*>(g_wh);
    float* accf = reinterpret_cast<float*>(g_hacc);

    float psum = 0.0f;
    for (int base = gw * 32; base < EE; base += EWARPS * 32) {
        int e = base + lane;
        int src = 0, dst = 0;
        float p = 0.0f;
        if (e < EE) {
            if (is64) {
                src = (int)ei64[e];
                dst = (int)ei64[EE + e];
            } else {
                src = ei32[e];
                dst = ei32[EE + e];
            }
            src = min(max(src, 0), NN - 1);
            dst = min(max(dst, 0), NN - 1);
            float s = g_ssrc[src] + g_sdst[dst];
            if (s > 0.0f) p = expf(s - B);
        }
        psum += p;

        unsigned act = __ballot_sync(0xffffffffu, p != 0.0f);
        while (act) {
            int j = __ffs(act) - 1;
            act &= act - 1;
            int sj = __shfl_sync(0xffffffffu, src, j);
            int dj = __shfl_sync(0xffffffffu, dst, j);
            float pj = __shfl_sync(0xffffffffu, p, j);
            const float* wr = whf + (size_t)sj * HIDD;
            float* ar = accf + (size_t)dj * HIDD;
            atomicAdd(ar + lane, pj * wr[lane]);
            atomicAdd(ar + 32 + lane, pj * wr[32 + lane]);
        }
    }

    // block-reduce psum
#pragma unroll
    for (int o = 16; o; o >>= 1) psum += __shfl_xor_sync(0xffffffffu, psum, o);
    __shared__ float sm[EWPB];
    if (lane == 0) sm[wid] = psum;
    __syncthreads();
    if (threadIdx.x == 0) {
        float t = 0.0f;
        for (int i = 0; i < EWPB; i++) t += sm[i];
        g_psum[blockIdx.x] = t;
    }
}

__global__ void k_reduce_sum() {
    float t = 0.0f;
    for (int i = threadIdx.x; i < EGRID; i += blockDim.x) t += g_psum[i];
#pragma unroll
    for (int o = 16; o; o >>= 1) t += __shfl_xor_sync(0xffffffffu, t, o);
    __shared__ float sm[8];
    int w = threadIdx.x >> 5;
    if ((threadIdx.x & 31) == 0) sm[w] = t;
    __syncthreads();
    if (threadIdx.x == 0) {
        float s = 0.0f;
        for (int i = 0; i < 8; i++) s += sm[i];
        g_red[1] = s;
    }
}

// ---------------- normalize + ELU ----------------
__global__ void k_elu_scale(int out_sel) {
    int t = blockIdx.x * blockDim.x + threadIdx.x;
    if (t >= NN * (HIDD / 4)) return;
    float s = g_red[1];
    float inv = (s > 0.0f) ? (1.0f / s) : 0.0f;
    float4 v = g_hacc[t];
    float4 r;
    float x;
    x = v.x * inv; r.x = (x > 0.0f) ? x : (expf(x) - 1.0f);
    x = v.y * inv; r.y = (x > 0.0f) ? x : (expf(x) - 1.0f);
    x = v.z * inv; r.z = (x > 0.0f) ? x : (expf(x) - 1.0f);
    x = v.w * inv; r.w = (x > 0.0f) ? x : (expf(x) - 1.0f);
    (out_sel ? g_h1 : g_h0)[t] = r;
}

// ---------------- output head: GEMM + ELU + log_softmax ----------------
__global__ void __launch_bounds__(128) k_out(const float* __restrict__ W,
                                             const float* __restrict__ b,
                                             float* __restrict__ out) {
    __shared__ float sW[HIDD * NC];
    __shared__ float sb[NC];
    int tid = threadIdx.x;
    for (int i = tid; i < HIDD * NC; i += blockDim.x) sW[i] = W[i];
    for (int i = tid; i < NC; i += blockDim.x) sb[i] = b[i];
    __syncthreads();

    int node = blockIdx.x * blockDim.x + tid;
    if (node >= NN) return;

    const float4* hr = g_h0 + (size_t)node * (HIDD / 4);

    float acc[NC];
#pragma unroll
    for (int j = 0; j < NC; j++) acc[j] = sb[j];

    for (int k4 = 0; k4 < HIDD / 4; k4++) {
        float4 hv = hr[k4];
        const float* w0 = &sW[(k4 * 4 + 0) * NC];
        const float* w1 = &sW[(k4 * 4 + 1) * NC];
        const float* w2 = &sW[(k4 * 4 + 2) * NC];
        const float* w3 = &sW[(k4 * 4 + 3) * NC];
#pragma unroll
        for (int j = 0; j < NC; j++)
            acc[j] += hv.x * w0[j] + hv.y * w1[j] + hv.z * w2[j] + hv.w * w3[j];
    }

    float mx = -3.4e38f;
#pragma unroll
    for (int j = 0; j < NC; j++) {
        float o = acc[j];
        o = (o > 0.0f) ? o : (expf(o) - 1.0f);   // ELU
        acc[j] = o;
        mx = fmaxf(mx, o);
    }
    float se = 0.0f;
#pragma unroll
    for (int j = 0; j < NC; j++) se += expf(acc[j] - mx);
    float lse = mx + logf(se);

    float* orow = out + (size_t)node * NC;
#pragma unroll
    for (int j = 0; j < NC; j++) orow[j] = acc[j] - lse;
}

// ---------------- launch ----------------
extern "C" void kernel_launch(void* const* d_in, const int* in_sizes, int n_in,
                              void* d_out, int out_size) {
    const float* x      = (const float*)d_in[0];
    const void*  ei     = (const void*)d_in[1];       // [2, E] int32 or int64
    const float* emb_w  = (const float*)d_in[2];
    const float* emb_b  = (const float*)d_in[3];
    const float* Ws     = (const float*)d_in[4];      // [2,64,64]
    const float* attn_a = (const float*)d_in[5];      // [2,1,128]
    const float* out_w  = (const float*)d_in[6];
    const float* out_b  = (const float*)d_in[7];
    float* out          = (float*)d_out;

    (void)in_sizes; (void)n_in; (void)out_size;

    const int TB = 128;
    const int nodeBlocks = (NN + TB - 1) / TB;
    const int zeroBlocks = (NN * (HIDD / 4) + 255) / 256;

    k_detect<<<1, 256>>>((const int*)ei);
    k_emb<<<nodeBlocks, TB>>>(x, emb_w, emb_b);

    for (int l = 0; l < 2; l++) {
        int in_sel  = (l == 0) ? 0 : 1;
        int out_sel = (l == 0) ? 1 : 0;
        k_gemm_s<<<nodeBlocks, TB>>>(in_sel, Ws + l * HIDD * HIDD, attn_a + l * 2 * HIDD);
        k_nodemax<<<NMAXBLK, 256>>>();
        k_reduce_shift<<<1, 128>>>();
        k_zero_hacc<<<zeroBlocks, 256>>>();
        k_edge<<<EGRID, ETPB>>>(ei);
        k_reduce_sum<<<1, 256>>>();
        k_elu_scale<<<zeroBlocks, 256>>>(out_sel);
    }

    k_out<<<nodeBlocks, TB>>>(out_w, out_b, out);
}

// round 4
// speedup vs baseline: 1.2168x; 1.2168x over previous
#include <cuda_runtime.h>

#define NN 100000
#define EE 1600000
#define IND 128
#define HIDD 64
#define NC 40

#define NBGS 782              // ceil(NN/128)
#define EGRID 1184
#define ETPB 256
#define EWPB (ETPB / 32)
#define EWARPS (EGRID * EWPB)

typedef unsigned long long ull;

// ---------------- device scratch ----------------
__device__ float4 g_h0[NN * (HIDD / 4)];    // embedding output
__device__ float4 g_h1[NN * (HIDD / 4)];    // layer-0 accumulator (raw)
__device__ float4 g_hacc[NN * (HIDD / 4)];  // layer-1 accumulator (raw)
__device__ float4 g_wh[NN * (HIDD / 4)];
__device__ float  g_ssrc[NN];
__device__ float  g_sdst[NN];
__device__ float  g_pmax_s[NBGS];
__device__ float  g_pmax_d[NBGS];
__device__ float  g_psum[EGRID];
__device__ float  g_red[2];   // [0] shift B, [1] softmax denominator
__device__ int    g_is64;
__device__ int2   g_epack[EE];

// ---------------- f32x2 helpers ----------------
__device__ __forceinline__ ull pk2(float a, float b) {
    ull r;
    asm("mov.b64 %0, {%1, %2};" : "=l"(r) : "f"(a), "f"(b));
    return r;
}
__device__ __forceinline__ ull dup2(float a) { return pk2(a, a); }
__device__ __forceinline__ float2 upk2(ull v) {
    float2 r;
    asm("mov.b64 {%0, %1}, %2;" : "=f"(r.x), "=f"(r.y) : "l"(v));
    return r;
}
__device__ __forceinline__ void ffma2(ull& acc, ull a, ull b) {
    asm("fma.rn.f32x2 %0, %1, %2, %0;" : "+l"(acc) : "l"(a), "l"(b));
}
__device__ __forceinline__ void red4(float* p, float a, float b, float c, float d) {
    asm volatile("red.global.add.v4.f32 [%0], {%1, %2, %3, %4};"
                 :: "l"(p), "f"(a), "f"(b), "f"(c), "f"(d) : "memory");
}
__device__ __forceinline__ float eluf(float x) { return x > 0.f ? x : (expf(x) - 1.f); }

// ---------------- dtype detect + index repack ----------------
__global__ void k_detect(const int* __restrict__ ei32) {
    int nz = 0;
    for (int i = threadIdx.x; i < 1024; i += blockDim.x)
        if (ei32[2 * i + 1] != 0) nz = 1;
    int cnt = __syncthreads_count(nz);
    if (threadIdx.x == 0) g_is64 = (cnt == 0) ? 1 : 0;
}

__global__ void k_prep(const void* __restrict__ ei_raw) {
    int e = blockIdx.x * blockDim.x + threadIdx.x;
    if (e >= EE) return;
    int s, d;
    if (g_is64) {
        s = (int)((const long long*)ei_raw)[e];
        d = (int)((const long long*)ei_raw)[EE + e];
    } else {
        s = ((const int*)ei_raw)[e];
        d = ((const int*)ei_raw)[EE + e];
    }
    s = min(max(s, 0), NN - 1);
    d = min(max(d, 0), NN - 1);
    g_epack[e] = make_int2(s, d);
}

// ---------------- embedding: h0 = x @ emb_w + emb_b (f32x2) ----------------
__global__ void __launch_bounds__(128) k_emb(const float* __restrict__ x,
                                             const float* __restrict__ w,
                                             const float* __restrict__ b) {
    __shared__ float sW[IND * HIDD];   // 32 KB
    __shared__ float sb[HIDD];
    int tid = threadIdx.x;
    for (int i = tid; i < IND * HIDD; i += 128) sW[i] = w[i];
    if (tid < HIDD) sb[tid] = b[tid];
    __syncthreads();

    int node = blockIdx.x * 128 + tid;
    if (node >= NN) return;

    ull acc2[32];
#pragma unroll
    for (int j = 0; j < 32; j++) acc2[j] = pk2(sb[2 * j], sb[2 * j + 1]);

    const float4* xr = reinterpret_cast<const float4*>(x + (size_t)node * IND);
#pragma unroll 2
    for (int k4 = 0; k4 < IND / 4; k4++) {
        float4 hv = xr[k4];
        float hk[4] = {hv.x, hv.y, hv.z, hv.w};
#pragma unroll
        for (int q = 0; q < 4; q++) {
            ull hp = dup2(hk[q]);
            const float4* wrow = reinterpret_cast<const float4*>(&sW[(k4 * 4 + q) * HIDD]);
#pragma unroll
            for (int j4 = 0; j4 < 16; j4++) {
                float4 wv = wrow[j4];
                ffma2(acc2[2 * j4], hp, pk2(wv.x, wv.y));
                ffma2(acc2[2 * j4 + 1], hp, pk2(wv.z, wv.w));
            }
        }
    }

    float4* orow = g_h0 + (size_t)node * 16;
#pragma unroll
    for (int j4 = 0; j4 < 16; j4++) {
        float2 a = upk2(acc2[2 * j4]);
        float2 c = upk2(acc2[2 * j4 + 1]);
        orow[j4] = make_float4(a.x, a.y, c.x, c.y);
    }
}

// ---------------- per-layer GEMM + scores + zero-acc + block max ----------------
// layer==0: read g_h0 raw,       zero g_h1
// layer==1: read g_h1 transformed (x*inv, ELU), zero g_hacc
__global__ void __launch_bounds__(128) k_gemm_s(int layer,
                                                const float* __restrict__ W,
                                                const float* __restrict__ avec) {
    __shared__ float sW[HIDD * HIDD];  // 16 KB
    __shared__ float sa[2 * HIDD];
    int tid = threadIdx.x;
    for (int i = tid; i < HIDD * HIDD; i += 128) sW[i] = W[i];
    if (tid < 2 * HIDD) sa[tid] = avec[tid];
    __syncthreads();

    int node = blockIdx.x * 128 + tid;
    float ssv = -3.4e38f, sdv = -3.4e38f;

    if (node < NN) {
        const float4* hr = (layer == 0 ? g_h0 : g_h1) + (size_t)node * 16;
        float4* az = (layer == 0 ? g_h1 : g_hacc) + (size_t)node * 16;

        float inv = 1.0f;
        if (layer) {
            float s = g_red[1];
            inv = (s > 0.0f) ? (1.0f / s) : 0.0f;
        }

        ull acc2[32];
#pragma unroll
        for (int j = 0; j < 32; j++) acc2[j] = 0ull;

#pragma unroll 4
        for (int k4 = 0; k4 < 16; k4++) {
            float4 hv = hr[k4];
            if (layer) {
                hv.x = eluf(hv.x * inv);
                hv.y = eluf(hv.y * inv);
                hv.z = eluf(hv.z * inv);
                hv.w = eluf(hv.w * inv);
            }
            float hk[4] = {hv.x, hv.y, hv.z, hv.w};
#pragma unroll
            for (int q = 0; q < 4; q++) {
                ull hp = dup2(hk[q]);
                const float4* wrow = reinterpret_cast<const float4*>(&sW[(k4 * 4 + q) * HIDD]);
#pragma unroll
                for (int j4 = 0; j4 < 16; j4++) {
                    float4 wv = wrow[j4];
                    ffma2(acc2[2 * j4], hp, pk2(wv.x, wv.y));
                    ffma2(acc2[2 * j4 + 1], hp, pk2(wv.z, wv.w));
                }
            }
        }

        // zero the accumulator this layer's edge pass will use
        float4 z = make_float4(0.f, 0.f, 0.f, 0.f);
#pragma unroll
        for (int j4 = 0; j4 < 16; j4++) az[j4] = z;

        float ss = 0.f, sd = 0.f;
        float4* wr = g_wh + (size_t)node * 16;
#pragma unroll
        for (int j4 = 0; j4 < 16; j4++) {
            float2 a = upk2(acc2[2 * j4]);
            float2 c = upk2(acc2[2 * j4 + 1]);
            ss += a.x * sa[4 * j4] + a.y * sa[4 * j4 + 1] + c.x * sa[4 * j4 + 2] + c.y * sa[4 * j4 + 3];
            sd += a.x * sa[HIDD + 4 * j4] + a.y * sa[HIDD + 4 * j4 + 1] +
                  c.x * sa[HIDD + 4 * j4 + 2] + c.y * sa[HIDD + 4 * j4 + 3];
            wr[j4] = make_float4(a.x, a.y, c.x, c.y);
        }
        g_ssrc[node] = ss;
        g_sdst[node] = sd;
        ssv = ss;
        sdv = sd;
    }

    // block max partials
#pragma unroll
    for (int o = 16; o; o >>= 1) {
        ssv = fmaxf(ssv, __shfl_xor_sync(0xffffffffu, ssv, o));
        sdv = fmaxf(sdv, __shfl_xor_sync(0xffffffffu, sdv, o));
    }
    __shared__ float sms[4], smd[4];
    int w = tid >> 5;
    if ((tid & 31) == 0) { sms[w] = ssv; smd[w] = sdv; }
    __syncthreads();
    if (tid == 0) {
        float a = fmaxf(fmaxf(sms[0], sms[1]), fmaxf(sms[2], sms[3]));
        float b = fmaxf(fmaxf(smd[0], smd[1]), fmaxf(smd[2], smd[3]));
        g_pmax_s[blockIdx.x] = a;
        g_pmax_d[blockIdx.x] = b;
    }
}

__global__ void k_reduce_shift() {
    float a = -3.4e38f, b = -3.4e38f;
    for (int i = threadIdx.x; i < NBGS; i += 256) {
        a = fmaxf(a, g_pmax_s[i]);
        b = fmaxf(b, g_pmax_d[i]);
    }
#pragma unroll
    for (int o = 16; o; o >>= 1) {
        a = fmaxf(a, __shfl_xor_sync(0xffffffffu, a, o));
        b = fmaxf(b, __shfl_xor_sync(0xffffffffu, b, o));
    }
    __shared__ float sa[8], sb[8];
    int w = threadIdx.x >> 5;
    if ((threadIdx.x & 31) == 0) { sa[w] = a; sb[w] = b; }
    __syncthreads();
    if (threadIdx.x == 0) {
        float ma = sa[0], mb = sb[0];
        for (int i = 1; i < 8; i++) { ma = fmaxf(ma, sa[i]); mb = fmaxf(mb, sb[i]); }
        g_red[0] = ma + mb;
    }
}

// ---------------- fused edge pass: exp, v4-red scatter, partial sum ----------------
__global__ void __launch_bounds__(ETPB) k_edge(int acc_sel) {
    const float B = g_red[0];
    int lane = threadIdx.x & 31;
    int wid = threadIdx.x >> 5;
    int gw = blockIdx.x * EWPB + wid;

    const float* whf = reinterpret_cast<const float*>(g_wh);
    float* accf = reinterpret_cast<float*>(acc_sel ? g_hacc : g_h1);

    float psum = 0.0f;
    for (int base = gw * 32; base < EE; base += EWARPS * 32) {
        int e = base + lane;
        int sx = 0, sy = 0;
        float p = 0.0f;
        if (e < EE) {
            int2 sd = g_epack[e];
            sx = sd.x; sy = sd.y;
            float s = g_ssrc[sx] + g_sdst[sy];
            if (s > 0.0f) p = expf(s - B);
        }
        psum += p;

        unsigned act = __ballot_sync(0xffffffffu, p != 0.0f);
        while (act) {
            int j0 = __ffs(act) - 1;
            act &= act - 1;
            int j1 = -1;
            if (act) { j1 = __ffs(act) - 1; act &= act - 1; }
            int j = (lane < 16) ? j0 : j1;
            int jj = (j < 0) ? 0 : j;
            int sj = __shfl_sync(0xffffffffu, sx, jj);
            int dj = __shfl_sync(0xffffffffu, sy, jj);
            float pj = __shfl_sync(0xffffffffu, p, jj);
            if (j >= 0) {
                int c = (lane & 15) * 4;
                const float4 wv = *reinterpret_cast<const float4*>(whf + (size_t)sj * HIDD + c);
                red4(accf + (size_t)dj * HIDD + c, pj * wv.x, pj * wv.y, pj * wv.z, pj * wv.w);
            }
        }
    }

#pragma unroll
    for (int o = 16; o; o >>= 1) psum += __shfl_xor_sync(0xffffffffu, psum, o);
    __shared__ float sm[EWPB];
    if (lane == 0) sm[wid] = psum;
    __syncthreads();
    if (threadIdx.x == 0) {
        float t = 0.0f;
        for (int i = 0; i < EWPB; i++) t += sm[i];
        g_psum[blockIdx.x] = t;
    }
}

__global__ void k_reduce_sum() {
    float t = 0.0f;
    for (int i = threadIdx.x; i < EGRID; i += 256) t += g_psum[i];
#pragma unroll
    for (int o = 16; o; o >>= 1) t += __shfl_xor_sync(0xffffffffu, t, o);
    __shared__ float sm[8];
    int w = threadIdx.x >> 5;
    if ((threadIdx.x & 31) == 0) sm[w] = t;
    __syncthreads();
    if (threadIdx.x == 0) {
        float s = 0.0f;
        for (int i = 0; i < 8; i++) s += sm[i];
        g_red[1] = s;
    }
}

// ---------------- output head: transform + GEMM + ELU + log_softmax ----------------
__global__ void __launch_bounds__(128) k_out(const float* __restrict__ W,
                                             const float* __restrict__ b,
                                             float* __restrict__ out) {
    __shared__ float sW[HIDD * NC];   // 10 KB
    __shared__ float sb[NC];
    int tid = threadIdx.x;
    for (int i = tid; i < HIDD * NC; i += 128) sW[i] = W[i];
    if (tid < NC) sb[tid] = b[tid];
    __syncthreads();

    int node = blockIdx.x * 128 + tid;
    if (node >= NN) return;

    float s = g_red[1];
    float inv = (s > 0.0f) ? (1.0f / s) : 0.0f;

    const float4* hr = g_hacc + (size_t)node * 16;

    ull acc2[NC / 2];
#pragma unroll
    for (int j = 0; j < NC / 2; j++) acc2[j] = pk2(sb[2 * j], sb[2 * j + 1]);

#pragma unroll 4
    for (int k4 = 0; k4 < 16; k4++) {
        float4 hv = hr[k4];
        hv.x = eluf(hv.x * inv);
        hv.y = eluf(hv.y * inv);
        hv.z = eluf(hv.z * inv);
        hv.w = eluf(hv.w * inv);
        float hk[4] = {hv.x, hv.y, hv.z, hv.w};
#pragma unroll
        for (int q = 0; q < 4; q++) {
            ull hp = dup2(hk[q]);
            const float4* wrow = reinterpret_cast<const float4*>(&sW[(k4 * 4 + q) * NC]);
#pragma unroll
            for (int j4 = 0; j4 < NC / 4; j4++) {
                float4 wv = wrow[j4];
                ffma2(acc2[2 * j4], hp, pk2(wv.x, wv.y));
                ffma2(acc2[2 * j4 + 1], hp, pk2(wv.z, wv.w));
            }
        }
    }

    float acc[NC];
#pragma unroll
    for (int j = 0; j < NC / 2; j++) {
        float2 v = upk2(acc2[j]);
        acc[2 * j] = v.x;
        acc[2 * j + 1] = v.y;
    }

    float mx = -3.4e38f;
#pragma unroll
    for (int j = 0; j < NC; j++) {
        float o = acc[j];
        o = (o > 0.0f) ? o : (expf(o) - 1.0f);
        acc[j] = o;
        mx = fmaxf(mx, o);
    }
    float se = 0.0f;
#pragma unroll
    for (int j = 0; j < NC; j++) se += expf(acc[j] - mx);
    float lse = mx + logf(se);

    float* orow = out + (size_t)node * NC;
#pragma unroll
    for (int j = 0; j < NC; j++) orow[j] = acc[j] - lse;
}

// ---------------- launch ----------------
extern "C" void kernel_launch(void* const* d_in, const int* in_sizes, int n_in,
                              void* d_out, int out_size) {
    const float* x      = (const float*)d_in[0];
    const void*  ei     = (const void*)d_in[1];
    const float* emb_w  = (const float*)d_in[2];
    const float* emb_b  = (const float*)d_in[3];
    const float* Ws     = (const float*)d_in[4];
    const float* attn_a = (const float*)d_in[5];
    const float* out_w  = (const float*)d_in[6];
    const float* out_b  = (const float*)d_in[7];
    float* out          = (float*)d_out;

    (void)in_sizes; (void)n_in; (void)out_size;

    k_detect<<<1, 256>>>((const int*)ei);
    k_prep<<<(EE + 255) / 256, 256>>>(ei);
    k_emb<<<NBGS, 128>>>(x, emb_w, emb_b);

    for (int l = 0; l < 2; l++) {
        k_gemm_s<<<NBGS, 128>>>(l, Ws + l * HIDD * HIDD, attn_a + l * 2 * HIDD);
        k_reduce_shift<<<1, 256>>>();
        k_edge<<<EGRID, ETPB>>>(l);
        k_reduce_sum<<<1, 256>>>();
    }

    k_out<<<NBGS, 128>>>(out_w, out_b, out);
}

// round 6
// speedup vs baseline: 1.2306x; 1.0114x over previous
#include <cuda_runtime.h>

#define NN 100000
#define EE 1600000
#define IND 128
#define HIDD 64
#define NC 40

#define NB2 391               // ceil(NN / 256) node blocks (256 nodes per block)
#define NTPB 256
#define EGRID 1184
#define ETPB 256
#define EWPB (ETPB / 32)
#define EWARPS (EGRID * EWPB)

typedef unsigned long long ull;

// ---------------- device scratch ----------------
__device__ float4 g_h0[NN * 16];     // embedding output
__device__ float4 g_h1[NN * 16];     // layer-0 accumulator (raw)
__device__ float4 g_hacc[NN * 16];   // layer-1 accumulator (raw)
__device__ float4 g_wh[NN * 16];
__device__ float  g_ssrc[NN];
__device__ float  g_sdst[NN];
__device__ float  g_pmax_s[NB2];
__device__ float  g_pmax_d[NB2];
__device__ float  g_psum[EGRID];
__device__ int    g_is64;
__device__ int2   g_epack[EE];

// ---------------- f32x2 helpers ----------------
__device__ __forceinline__ ull pk2(float a, float b) {
    ull r;
    asm("mov.b64 %0, {%1, %2};" : "=l"(r) : "f"(a), "f"(b));
    return r;
}
__device__ __forceinline__ ull dup2(float a) { return pk2(a, a); }
__device__ __forceinline__ float2 upk2(ull v) {
    float2 r;
    asm("mov.b64 {%0, %1}, %2;" : "=f"(r.x), "=f"(r.y) : "l"(v));
    return r;
}
__device__ __forceinline__ void ffma2(ull& acc, ull a, ull b) {
    asm("fma.rn.f32x2 %0, %1, %2, %0;" : "+l"(acc) : "l"(a), "l"(b));
}
__device__ __forceinline__ void red4(float* p, float a, float b, float c, float d) {
    asm volatile("red.global.add.v4.f32 [%0], {%1, %2, %3, %4};"
                 :: "l"(p), "f"(a), "f"(b), "f"(c), "f"(d) : "memory");
}
__device__ __forceinline__ float eluf(float x) { return x > 0.f ? x : (expf(x) - 1.f); }

// ---------------- dtype detect + index repack ----------------
__global__ void k_detect(const int* __restrict__ ei32) {
    int nz = 0;
    for (int i = threadIdx.x; i < 1024; i += blockDim.x)
        if (ei32[2 * i + 1] != 0) nz = 1;
    int cnt = __syncthreads_count(nz);
    if (threadIdx.x == 0) g_is64 = (cnt == 0) ? 1 : 0;
}

__global__ void k_prep(const void* __restrict__ ei_raw) {
    int e = blockIdx.x * blockDim.x + threadIdx.x;
    if (e >= EE) return;
    int s, d;
    if (g_is64) {
        s = (int)((const long long*)ei_raw)[e];
        d = (int)((const long long*)ei_raw)[EE + e];
    } else {
        s = ((const int*)ei_raw)[e];
        d = ((const int*)ei_raw)[EE + e];
    }
    s = min(max(s, 0), NN - 1);
    d = min(max(d, 0), NN - 1);
    g_epack[e] = make_int2(s, d);
}

// ---------------- embedding: h0 = x @ emb_w + emb_b ----------------
// 256 threads, 256 nodes/block: pair = tid>>1 -> nodes n0,n0+1 ; jh = tid&1 -> 32 output cols
__global__ void __launch_bounds__(NTPB) k_emb(const float* __restrict__ x,
                                              const float* __restrict__ w,
                                              const float* __restrict__ b) {
    __shared__ float4 sW4[IND * HIDD / 4];   // 32 KB
    __shared__ float sb[HIDD];
    int tid = threadIdx.x;
    const float4* wg = reinterpret_cast<const float4*>(w);
    for (int i = tid; i < IND * HIDD / 4; i += NTPB) sW4[i] = wg[i];
    if (tid < HIDD) sb[tid] = b[tid];
    __syncthreads();

    int jh = tid & 1;
    int n0 = blockIdx.x * 256 + (tid >> 1) * 2;
    if (n0 >= NN) return;

    ull a0[16], a1[16];
#pragma unroll
    for (int j = 0; j < 16; j++) {
        float lo = sb[jh * 32 + 2 * j], hi = sb[jh * 32 + 2 * j + 1];
        a0[j] = pk2(lo, hi);
        a1[j] = pk2(lo, hi);
    }

    const float4* x0 = reinterpret_cast<const float4*>(x + (size_t)n0 * IND);
    const float4* x1 = reinterpret_cast<const float4*>(x + (size_t)(n0 + 1) * IND);
    const char* wbase = reinterpret_cast<const char*>(sW4) + jh * 128;

    float h0a[4], h1a[4];
#pragma unroll 8
    for (int k = 0; k < IND; k++) {
        if ((k & 3) == 0) {
            float4 f0 = x0[k >> 2], f1 = x1[k >> 2];
            h0a[0] = f0.x; h0a[1] = f0.y; h0a[2] = f0.z; h0a[3] = f0.w;
            h1a[0] = f1.x; h1a[1] = f1.y; h1a[2] = f1.z; h1a[3] = f1.w;
        }
        ull hp0 = dup2(h0a[k & 3]);
        ull hp1 = dup2(h1a[k & 3]);
        const ulonglong2* wrow = reinterpret_cast<const ulonglong2*>(wbase + k * (HIDD * 4));
#pragma unroll
        for (int j = 0; j < 8; j++) {
            ulonglong2 wv = wrow[j];
            ffma2(a0[2 * j], hp0, wv.x);
            ffma2(a0[2 * j + 1], hp0, wv.y);
            ffma2(a1[2 * j], hp1, wv.x);
            ffma2(a1[2 * j + 1], hp1, wv.y);
        }
    }

    float4* o0 = g_h0 + (size_t)n0 * 16 + jh * 8;
    float4* o1 = g_h0 + (size_t)(n0 + 1) * 16 + jh * 8;
#pragma unroll
    for (int q = 0; q < 8; q++) {
        float2 u = upk2(a0[2 * q]), v = upk2(a0[2 * q + 1]);
        o0[q] = make_float4(u.x, u.y, v.x, v.y);
        u = upk2(a1[2 * q]); v = upk2(a1[2 * q + 1]);
        o1[q] = make_float4(u.x, u.y, v.x, v.y);
    }
}

// ---------------- per-layer GEMM + scores + zero-acc + block max ----------------
__global__ void __launch_bounds__(NTPB) k_gemm_s(int layer,
                                                 const float* __restrict__ W,
                                                 const float* __restrict__ avec) {
    __shared__ float4 sW4[HIDD * HIDD / 4];  // 16 KB
    __shared__ float sa[2 * HIDD];
    __shared__ float sInv;
    int tid = threadIdx.x;
    const float4* wg = reinterpret_cast<const float4*>(W);
    for (int i = tid; i < HIDD * HIDD / 4; i += NTPB) sW4[i] = wg[i];
    if (tid < 2 * HIDD) sa[tid] = avec[tid];

    if (layer) {
        // redundant deterministic reduce of layer-0 softmax denominator
        float t = 0.0f;
        for (int i = tid; i < EGRID; i += NTPB) t += g_psum[i];
#pragma unroll
        for (int o = 16; o; o >>= 1) t += __shfl_xor_sync(0xffffffffu, t, o);
        __shared__ float sm[8];
        if ((tid & 31) == 0) sm[tid >> 5] = t;
        __syncthreads();
        if (tid == 0) {
            float s = 0.0f;
            for (int i = 0; i < 8; i++) s += sm[i];
            sInv = (s > 0.0f) ? (1.0f / s) : 0.0f;
        }
    }
    __syncthreads();
    float inv = layer ? sInv : 1.0f;

    int jh = tid & 1;
    int n0 = blockIdx.x * 256 + (tid >> 1) * 2;
    bool act = (n0 < NN);
    int n0c = act ? n0 : 0;

    ull a0[16], a1[16];
#pragma unroll
    for (int j = 0; j < 16; j++) { a0[j] = 0ull; a1[j] = 0ull; }

    const float4* h0 = (layer ? g_h1 : g_h0) + (size_t)n0c * 16;
    const float4* h1 = (layer ? g_h1 : g_h0) + (size_t)(n0c + 1) * 16;
    const char* wbase = reinterpret_cast<const char*>(sW4) + jh * 128;

    float h0a[4], h1a[4];
#pragma unroll 8
    for (int k = 0; k < HIDD; k++) {
        if ((k & 3) == 0) {
            float4 f0 = h0[k >> 2], f1 = h1[k >> 2];
            if (layer) {
                f0.x = eluf(f0.x * inv); f0.y = eluf(f0.y * inv);
                f0.z = eluf(f0.z * inv); f0.w = eluf(f0.w * inv);
                f1.x = eluf(f1.x * inv); f1.y = eluf(f1.y * inv);
                f1.z = eluf(f1.z * inv); f1.w = eluf(f1.w * inv);
            }
            h0a[0] = f0.x; h0a[1] = f0.y; h0a[2] = f0.z; h0a[3] = f0.w;
            h1a[0] = f1.x; h1a[1] = f1.y; h1a[2] = f1.z; h1a[3] = f1.w;
        }
        ull hp0 = dup2(h0a[k & 3]);
        ull hp1 = dup2(h1a[k & 3]);
        const ulonglong2* wrow = reinterpret_cast<const ulonglong2*>(wbase + k * (HIDD * 4));
#pragma unroll
        for (int j = 0; j < 8; j++) {
            ulonglong2 wv = wrow[j];
            ffma2(a0[2 * j], hp0, wv.x);
            ffma2(a0[2 * j + 1], hp0, wv.y);
            ffma2(a1[2 * j], hp1, wv.x);
            ffma2(a1[2 * j + 1], hp1, wv.y);
        }
    }

    // partial attention dots over this thread's 32 columns
    float ssp0 = 0.f, sdp0 = 0.f, ssp1 = 0.f, sdp1 = 0.f;
#pragma unroll
    for (int j = 0; j < 16; j++) {
        float as0 = sa[jh * 32 + 2 * j], as1 = sa[jh * 32 + 2 * j + 1];
        float ad0 = sa[HIDD + jh * 32 + 2 * j], ad1 = sa[HIDD + jh * 32 + 2 * j + 1];
        float2 v0 = upk2(a0[j]);
        float2 v1 = upk2(a1[j]);
        ssp0 += v0.x * as0 + v0.y * as1;
        sdp0 += v0.x * ad0 + v0.y * ad1;
        ssp1 += v1.x * as0 + v1.y * as1;
        sdp1 += v1.x * ad0 + v1.y * ad1;
    }
    float ss0 = ssp0 + __shfl_xor_sync(0xffffffffu, ssp0, 1);
    float sd0 = sdp0 + __shfl_xor_sync(0xffffffffu, sdp0, 1);
    float ss1 = ssp1 + __shfl_xor_sync(0xffffffffu, ssp1, 1);
    float sd1 = sdp1 + __shfl_xor_sync(0xffffffffu, sdp1, 1);

    if (act) {
        if (jh == 0) {
            g_ssrc[n0] = ss0; g_sdst[n0] = sd0;
            g_ssrc[n0 + 1] = ss1; g_sdst[n0 + 1] = sd1;
        }
        // write wh halves + zero accumulator halves
        float4* w0 = g_wh + (size_t)n0 * 16 + jh * 8;
        float4* w1 = g_wh + (size_t)(n0 + 1) * 16 + jh * 8;
        float4* z0 = (layer ? g_hacc : g_h1) + (size_t)n0 * 16 + jh * 8;
        float4* z1 = (layer ? g_hacc : g_h1) + (size_t)(n0 + 1) * 16 + jh * 8;
        float4 z = make_float4(0.f, 0.f, 0.f, 0.f);
#pragma unroll
        for (int q = 0; q < 8; q++) {
            float2 u = upk2(a0[2 * q]), v = upk2(a0[2 * q + 1]);
            w0[q] = make_float4(u.x, u.y, v.x, v.y);
            u = upk2(a1[2 * q]); v = upk2(a1[2 * q + 1]);
            w1[q] = make_float4(u.x, u.y, v.x, v.y);
            z0[q] = z; z1[q] = z;
        }
    }

    // block max partials
    float ms = act ? fmaxf(ss0, ss1) : -3.4e38f;
    float md = act ? fmaxf(sd0, sd1) : -3.4e38f;
#pragma unroll
    for (int o = 16; o; o >>= 1) {
        ms = fmaxf(ms, __shfl_xor_sync(0xffffffffu, ms, o));
        md = fmaxf(md, __shfl_xor_sync(0xffffffffu, md, o));
    }
    __shared__ float sms[8], smd[8];
    if ((tid & 31) == 0) { sms[tid >> 5] = ms; smd[tid >> 5] = md; }
    __syncthreads();
    if (tid == 0) {
        float a = sms[0], b = smd[0];
        for (int i = 1; i < 8; i++) { a = fmaxf(a, sms[i]); b = fmaxf(b, smd[i]); }
        g_pmax_s[blockIdx.x] = a;
        g_pmax_d[blockIdx.x] = b;
    }
}

// ---------------- fused edge pass ----------------
__global__ void __launch_bounds__(ETPB) k_edge(int acc_sel) {
    // redundant deterministic reduce of shift B
    __shared__ float sB;
    {
        float a = -3.4e38f, b = -3.4e38f;
        for (int i = threadIdx.x; i < NB2; i += ETPB) {
            a = fmaxf(a, g_pmax_s[i]);
            b = fmaxf(b, g_pmax_d[i]);
        }
#pragma unroll
        for (int o = 16; o; o >>= 1) {
            a = fmaxf(a, __shfl_xor_sync(0xffffffffu, a, o));
            b = fmaxf(b, __shfl_xor_sync(0xffffffffu, b, o));
        }
        __shared__ float ra[EWPB], rb[EWPB];
        if ((threadIdx.x & 31) == 0) { ra[threadIdx.x >> 5] = a; rb[threadIdx.x >> 5] = b; }
        __syncthreads();
        if (threadIdx.x == 0) {
            float ma = ra[0], mb = rb[0];
            for (int i = 1; i < EWPB; i++) { ma = fmaxf(ma, ra[i]); mb = fmaxf(mb, rb[i]); }
            sB = ma + mb;
        }
        __syncthreads();
    }
    const float B = sB;

    int lane = threadIdx.x & 31;
    int wid = threadIdx.x >> 5;
    int gw = blockIdx.x * EWPB + wid;

    const float* whf = reinterpret_cast<const float*>(g_wh);
    float* accf = reinterpret_cast<float*>(acc_sel ? g_hacc : g_h1);

    float psum = 0.0f;
    for (int base = gw * 32; base < EE; base += EWARPS * 32) {
        int e = base + lane;
        int sx = 0, sy = 0;
        float p = 0.0f;
        if (e < EE) {
            int2 sd = g_epack[e];
            sx = sd.x; sy = sd.y;
            float s = g_ssrc[sx] + g_sdst[sy];
            if (s > 0.0f) p = expf(s - B);
        }
        psum += p;

        unsigned actm = __ballot_sync(0xffffffffu, p != 0.0f);
        while (actm) {
            int j0 = __ffs(actm) - 1;
            actm &= actm - 1;
            int j1 = -1;
            if (actm) { j1 = __ffs(actm) - 1; actm &= actm - 1; }
            int j = (lane < 16) ? j0 : j1;
            int jj = (j < 0) ? 0 : j;
            int sj = __shfl_sync(0xffffffffu, sx, jj);
            int dj = __shfl_sync(0xffffffffu, sy, jj);
            float pj = __shfl_sync(0xffffffffu, p, jj);
            if (j >= 0) {
                int c = (lane & 15) * 4;
                const float4 wv = *reinterpret_cast<const float4*>(whf + (size_t)sj * HIDD + c);
                red4(accf + (size_t)dj * HIDD + c, pj * wv.x, pj * wv.y, pj * wv.z, pj * wv.w);
            }
        }
    }

#pragma unroll
    for (int o = 16; o; o >>= 1) psum += __shfl_xor_sync(0xffffffffu, psum, o);
    __shared__ float sm2[EWPB];
    if (lane == 0) sm2[wid] = psum;
    __syncthreads();
    if (threadIdx.x == 0) {
        float t = 0.0f;
        for (int i = 0; i < EWPB; i++) t += sm2[i];
        g_psum[blockIdx.x] = t;
    }
}

// ---------------- output head: transform + GEMM + ELU + log_softmax ----------------
__global__ void __launch_bounds__(NTPB) k_out(const float* __restrict__ W,
                                              const float* __restrict__ b,
                                              float* __restrict__ out) {
    __shared__ __align__(16) float sW[HIDD * NC];   // 10 KB
    __shared__ float sb[NC];
    __shared__ float sInv;
    int tid = threadIdx.x;
    for (int i = tid; i < HIDD * NC; i += NTPB) sW[i] = W[i];
    if (tid < NC) sb[tid] = b[tid];
    {
        float t = 0.0f;
        for (int i = tid; i < EGRID; i += NTPB) t += g_psum[i];
#pragma unroll
        for (int o = 16; o; o >>= 1) t += __shfl_xor_sync(0xffffffffu, t, o);
        __shared__ float sm[8];
        if ((tid & 31) == 0) sm[tid >> 5] = t;
        __syncthreads();
        if (tid == 0) {
            float s = 0.0f;
            for (int i = 0; i < 8; i++) s += sm[i];
            sInv = (s > 0.0f) ? (1.0f / s) : 0.0f;
        }
    }
    __syncthreads();
    float inv = sInv;

    int jh = tid & 1;
    int n0 = blockIdx.x * 256 + (tid >> 1) * 2;
    if (n0 >= NN) return;

    ull a0[10], a1[10];
#pragma unroll
    for (int j = 0; j < 10; j++) {
        float lo = sb[jh * 20 + 2 * j], hi = sb[jh * 20 + 2 * j + 1];
        a0[j] = pk2(lo, hi);
        a1[j] = pk2(lo, hi);
    }

    const float4* h0 = g_hacc + (size_t)n0 * 16;
    const float4* h1 = g_hacc + (size_t)(n0 + 1) * 16;
    const char* wbase = reinterpret_cast<const char*>(sW) + jh * 80;

    float h0a[4], h1a[4];
#pragma unroll 8
    for (int k = 0; k < HIDD; k++) {
        if ((k & 3) == 0) {
            float4 f0 = h0[k >> 2], f1 = h1[k >> 2];
            f0.x = eluf(f0.x * inv); f0.y = eluf(f0.y * inv);
            f0.z = eluf(f0.z * inv); f0.w = eluf(f0.w * inv);
            f1.x = eluf(f1.x * inv); f1.y = eluf(f1.y * inv);
            f1.z = eluf(f1.z * inv); f1.w = eluf(f1.w * inv);
            h0a[0] = f0.x; h0a[1] = f0.y; h0a[2] = f0.z; h0a[3] = f0.w;
            h1a[0] = f1.x; h1a[1] = f1.y; h1a[2] = f1.z; h1a[3] = f1.w;
        }
        ull hp0 = dup2(h0a[k & 3]);
        ull hp1 = dup2(h1a[k & 3]);
        const ulonglong2* wrow = reinterpret_cast<const ulonglong2*>(wbase + k * (NC * 4));
#pragma unroll
        for (int j = 0; j < 5; j++) {
            ulonglong2 wv = wrow[j];
            ffma2(a0[2 * j], hp0, wv.x);
            ffma2(a0[2 * j + 1], hp0, wv.y);
            ffma2(a1[2 * j], hp1, wv.x);
            ffma2(a1[2 * j + 1], hp1, wv.y);
        }
    }

    float v0[20], v1[20];
#pragma unroll
    for (int j = 0; j < 10; j++) {
        float2 u = upk2(a0[j]); v0[2 * j] = u.x; v0[2 * j + 1] = u.y;
        u = upk2(a1[j]); v1[2 * j] = u.x; v1[2 * j + 1] = u.y;
    }

    float m0 = -3.4e38f, m1 = -3.4e38f;
#pragma unroll
    for (int j = 0; j < 20; j++) {
        v0[j] = (v0[j] > 0.f) ? v0[j] : (expf(v0[j]) - 1.f);
        v1[j] = (v1[j] > 0.f) ? v1[j] : (expf(v1[j]) - 1.f);
        m0 = fmaxf(m0, v0[j]);
        m1 = fmaxf(m1, v1[j]);
    }
    m0 = fmaxf(m0, __shfl_xor_sync(0xffffffffu, m0, 1));
    m1 = fmaxf(m1, __shfl_xor_sync(0xffffffffu, m1, 1));

    float se0 = 0.f, se1 = 0.f;
#pragma unroll
    for (int j = 0; j < 20; j++) {
        se0 += expf(v0[j] - m0);
        se1 += expf(v1[j] - m1);
    }
    se0 += __shfl_xor_sync(0xffffffffu, se0, 1);
    se1 += __shfl_xor_sync(0xffffffffu, se1, 1);
    float lse0 = m0 + logf(se0);
    float lse1 = m1 + logf(se1);

    float* o0 = out + (size_t)n0 * NC + jh * 20;
    float* o1 = out + (size_t)(n0 + 1) * NC + jh * 20;
#pragma unroll
    for (int j = 0; j < 20; j++) {
        o0[j] = v0[j] - lse0;
        o1[j] = v1[j] - lse1;
    }
}

// ---------------- launch ----------------
extern "C" void kernel_launch(void* const* d_in, const int* in_sizes, int n_in,
                              void* d_out, int out_size) {
    const float* x      = (const float*)d_in[0];
    const void*  ei     = (const void*)d_in[1];
    const float* emb_w  = (const float*)d_in[2];
    const float* emb_b  = (const float*)d_in[3];
    const float* Ws     = (const float*)d_in[4];
    const float* attn_a = (const float*)d_in[5];
    const float* out_w  = (const float*)d_in[6];
    const float* out_b  = (const float*)d_in[7];
    float* out          = (float*)d_out;

    (void)in_sizes; (void)n_in; (void)out_size;

    k_detect<<<1, 256>>>((const int*)ei);
    k_prep<<<(EE + 255) / 256, 256>>>(ei);
    k_emb<<<NB2, NTPB>>>(x, emb_w, emb_b);

    for (int l = 0; l < 2; l++) {
        k_gemm_s<<<NB2, NTPB>>>(l, Ws + l * HIDD * HIDD, attn_a + l * 2 * HIDD);
        k_edge<<<EGRID, ETPB>>>(l);
    }

    k_out<<<NB2, NTPB>>>(out_w, out_b, out);
}